// round 10
// baseline (speedup 1.0000x reference)
#include <cuda_runtime.h>
#include <cuda_bf16.h>
#include <cstdint>

#define L_TOT    524288
#define M_TOT    (L_TOT / 4)
#define NBATCH   16
#define TILE_Y   4096
#define NTILES   (L_TOT / TILE_Y)      // 128
#define NTASKS   (NTILES * NBATCH)     // 2048

// xs: 4224 fp32 -> 2112 bf16-pair words; skewed: 2112 + 4*(2112/16) = 2640
#define XS_WORDS   2640
#define BS_STRIDE  100                 // words per c-row (100 mod 32 = 4)
#define BS_WORDS   (32 * BS_STRIDE)

// B operand (bf16-pair packed, hi/lo) staged via device globals
__device__ uint32_t g_Bh[32 * 80];
__device__ uint32_t g_Bl[32 * 80];

__device__ __forceinline__ void mma16816(float* d, const uint32_t* a,
                                         uint32_t b0, uint32_t b1) {
    asm volatile(
        "mma.sync.aligned.m16n8k16.row.col.f32.bf16.bf16.f32 "
        "{%0,%1,%2,%3}, {%4,%5,%6,%7}, {%8,%9}, {%0,%1,%2,%3};"
        : "+f"(d[0]), "+f"(d[1]), "+f"(d[2]), "+f"(d[3])
        : "r"(a[0]), "r"(a[1]), "r"(a[2]), "r"(a[3]), "r"(b0), "r"(b1));
}

// ---------------------------------------------------------------------------
// edge kernel: exact two-stage edges + builds B table (32 blocks x 80 entries)
// ---------------------------------------------------------------------------
__global__ void pqmf_edge_kernel(const float* __restrict__ x,
                                 const float* __restrict__ qmf,
                                 float* __restrict__ y) {
    __shared__ float s_q[260];
    __shared__ float s_sub[4][16];
    __shared__ float s_part[128];

    const int side = blockIdx.x;          // 0 = low edge, 1 = high edge
    const int b    = blockIdx.y;
    const float* xb = x + (size_t)b * L_TOT;
    float*       yb = y + (size_t)b * L_TOT;
    const int tid = threadIdx.x;          // 128 threads

    for (int i = tid; i < 260; i += 128) s_q[i] = qmf[i];
    __syncthreads();

    // ---- build B[c][k] = C[c&3][k-c], bf16 hi/lo pair-packed --------------
    // 32 blocks cover 2560 pair-entries; this block owns 80 of them.
    {
        const int bid = blockIdx.y * 2 + blockIdx.x;    // 0..31
        const int base = bid * 80;
        for (int e = tid; e < 80; e += 128) {
            int idx = base + e;
            int c = idx / 80, kp = idx % 80;
            float v[2];
            #pragma unroll
            for (int u = 0; u < 2; u++) {
                int k = 2 * kp + u, dd = k - c;
                float val = 0.f;
                if (dd >= 0 && dd <= 128) {
                    int r = c & 3, t0 = (4 - r) & 3;
                    for (int t = t0; t <= 64; t += 4) {
                        int s = dd - t;
                        if (s >= 0 && s <= 64) {
                            #pragma unroll
                            for (int q = 0; q < 4; q++)
                                val += s_q[q * 65 + t] * s_q[q * 65 + s];
                        }
                    }
                }
                v[u] = val;
            }
            __nv_bfloat16 h0 = __float2bfloat16(v[0]);
            __nv_bfloat16 h1 = __float2bfloat16(v[1]);
            __nv_bfloat16 l0 = __float2bfloat16(v[0] - __bfloat162float(h0));
            __nv_bfloat16 l1 = __float2bfloat16(v[1] - __bfloat162float(h1));
            g_Bh[idx] = ((uint32_t)__bfloat16_as_ushort(h1) << 16) |
                        __bfloat16_as_ushort(h0);
            g_Bl[idx] = ((uint32_t)__bfloat16_as_ushort(l1) << 16) |
                        __bfloat16_as_ushort(l0);
        }
    }

    // ---- exact edges --------------------------------------------------------
    const int mbase = side ? (M_TOT - 16) : 0;
    if (tid < 64) {
        int k = tid & 3, j = tid >> 2;
        int m = mbase + j;
        float sub = 0.f;
        int pbase = 4 * m - 32;
        for (int s = 0; s <= 64; s++) {
            int pos = pbase + s;
            if (pos >= 0 && pos < L_TOT)
                sub = fmaf(s_q[k * 65 + s], xb[pos], sub);
        }
        s_sub[k][j] = sub;
    }
    __syncthreads();

    float partial = 0.f;
    {
        int nn = tid >> 2, k = tid & 3;
        int n  = side ? (L_TOT - 32 + nn) : nn;
        int t0 = (4 - (n & 3)) & 3;
        for (int t = t0; t <= 64; t += 4) {
            int m = (n + t - 32) >> 2;
            if (m < 0 || m >= M_TOT) continue;
            partial = fmaf(s_q[k * 65 + t], s_sub[k][m - mbase], partial);
        }
    }
    s_part[tid] = partial;
    __syncthreads();
    if (tid < 32) {
        int n = side ? (L_TOT - 32 + tid) : tid;
        yb[n] = s_part[tid * 4] + s_part[tid * 4 + 1] +
                s_part[tid * 4 + 2] + s_part[tid * 4 + 3];
    }
}

// ---------------------------------------------------------------------------
// main: bf16 mma.sync GEMM on the Toeplitz view of x (3-pass hi/lo)
// one task per CTA (grid = 2048) for balanced scheduling
// ---------------------------------------------------------------------------
__global__ __launch_bounds__(256, 4)
void pqmf_mma_kernel(const float* __restrict__ x, float* __restrict__ y) {
    __shared__ uint32_t xs_h[XS_WORDS], xs_l[XS_WORDS];
    __shared__ uint32_t bs_h[BS_WORDS], bs_l[BS_WORDS];

    const int tid  = threadIdx.x;
    const int wt   = tid >> 5;     // warp = m-tile (16 rows)
    const int lane = tid & 31;
    const int g    = lane >> 2;    // groupID
    const int tg   = lane & 3;     // threadID-in-group

    const int task = blockIdx.x;
    const int tile = task & (NTILES - 1);
    const int b    = task >> 7;
    const int t0   = tile * TILE_Y;
    const float* xb = x + (size_t)b * L_TOT;
    float*       yb = y + (size_t)b * L_TOT;

    // stage B (pair word kp of row c at bs[c*100 + kp]) — L2-resident
    for (int i = tid; i < 32 * 80; i += 256) {
        int c = i / 80, kp = i % 80;
        bs_h[c * BS_STRIDE + kp] = g_Bh[i];
        bs_l[c * BS_STRIDE + kp] = g_Bl[i];
    }

    // stage x tile: element pair i2 -> skewed word i2 + 4*(i2>>4)
    for (int i2 = tid; i2 < 2112; i2 += 256) {
        int pos = t0 - 64 + 2 * i2;
        float v0 = 0.f, v1 = 0.f;
        if (pos >= 0 && pos + 1 < L_TOT) {
            float2 xv = *reinterpret_cast<const float2*>(xb + pos);
            v0 = xv.x; v1 = xv.y;
        } else {
            if (pos >= 0 && pos < L_TOT)         v0 = xb[pos];
            if (pos + 1 >= 0 && pos + 1 < L_TOT) v1 = xb[pos + 1];
        }
        __nv_bfloat16 h0 = __float2bfloat16(v0);
        __nv_bfloat16 h1 = __float2bfloat16(v1);
        __nv_bfloat16 l0 = __float2bfloat16(v0 - __bfloat162float(h0));
        __nv_bfloat16 l1 = __float2bfloat16(v1 - __bfloat162float(h1));
        int pw = i2 + 4 * (i2 >> 4);
        xs_h[pw] = ((uint32_t)__bfloat16_as_ushort(h1) << 16) |
                   __bfloat16_as_ushort(h0);
        xs_l[pw] = ((uint32_t)__bfloat16_as_ushort(l1) << 16) |
                   __bfloat16_as_ushort(l0);
    }
    __syncthreads();

    const int PA = 320 * wt + 20 * g + tg;   // A fragment phys base (words)

    float d[4][4];
    #pragma unroll
    for (int nt = 0; nt < 4; nt++)
        #pragma unroll
        for (int q = 0; q < 4; q++) d[nt][q] = 0.f;

    #pragma unroll
    for (int s = 0; s < 10; s++) {
        const int pw = PA + 8 * s + 4 * (s >> 1);   // compile-time offset
        uint32_t ah[4], al[4];
        ah[0] = xs_h[pw];       ah[2] = xs_h[pw + 4];
        ah[1] = xs_h[pw + 160]; ah[3] = xs_h[pw + 164];
        al[0] = xs_l[pw];       al[2] = xs_l[pw + 4];
        al[1] = xs_l[pw + 160]; al[3] = xs_l[pw + 164];
        #pragma unroll
        for (int nt = 0; nt < 4; nt++) {
            const int pb = 800 * nt + 100 * g + tg + 8 * s;
            uint32_t bh0 = bs_h[pb], bh1 = bs_h[pb + 4];
            uint32_t bl0 = bs_l[pb], bl1 = bs_l[pb + 4];
            mma16816(d[nt], ah, bh0, bh1);   // hi*hi
            mma16816(d[nt], al, bh0, bh1);   // lo*hi
            mma16816(d[nt], ah, bl0, bl1);   // hi*lo
        }
    }

    // epilogue: d[nt] rows (16wt+g, +8), cols 8nt + 2tg + {0,1}
    const int row0 = 16 * wt + g;
    const bool skip_lo = (tile == 0) && (row0 == 0);
    const bool skip_hi = (tile == NTILES - 1) && (row0 + 8 == 127);
    #pragma unroll
    for (int nt = 0; nt < 4; nt++) {
        int n_lo = t0 + 32 * row0 + 8 * nt + 2 * tg;
        if (!skip_lo)
            *reinterpret_cast<float2*>(yb + n_lo) =
                make_float2(d[nt][0], d[nt][1]);
        if (!skip_hi)
            *reinterpret_cast<float2*>(yb + n_lo + 256) =
                make_float2(d[nt][2], d[nt][3]);
    }
}

extern "C" void kernel_launch(void* const* d_in, const int* in_sizes, int n_in,
                              void* d_out, int out_size) {
    const float* x   = (const float*)d_in[0];
    const float* qmf = (const float*)d_in[1];
    if (n_in >= 2 && in_sizes[0] == 260) {
        x   = (const float*)d_in[1];
        qmf = (const float*)d_in[0];
    }
    float* y = (float*)d_out;

    pqmf_edge_kernel<<<dim3(2, NBATCH), 128>>>(x, qmf, y);
    pqmf_mma_kernel<<<NTASKS, 256>>>(x, y);
}

// round 12
// speedup vs baseline: 1.0530x; 1.0530x over previous
#include <cuda_runtime.h>
#include <cuda_bf16.h>
#include <cstdint>

#define L_TOT    524288
#define M_TOT    (L_TOT / 4)
#define NBATCH   16
#define TILE_Y   4096
#define NTILES   (L_TOT / TILE_Y)      // 128
#define NTASKS   (NTILES * NBATCH)     // 2048

// xs: 4224 fp32 -> 2112 bf16-pair words; skewed: 2112 + 4*(2112/16) = 2640
#define XS_WORDS   2640
#define BS_STRIDE  100                 // words per c-row (100 mod 32 = 4)
#define BS_WORDS   (32 * BS_STRIDE)

// B operand (bf16-pair packed, hi/lo) staged via device globals
__device__ uint32_t g_Bh[32 * 80];
__device__ uint32_t g_Bl[32 * 80];

__device__ __forceinline__ uint32_t smem_u32(const void* p) {
    uint32_t a;
    asm("{ .reg .u64 t; cvta.to.shared.u64 t, %1; cvt.u32.u64 %0, t; }"
        : "=r"(a) : "l"(p));
    return a;
}

#define LDSM_X4(r, a)                                                        \
    asm volatile("ldmatrix.sync.aligned.m8n8.x4.shared.b16 "                 \
                 "{%0,%1,%2,%3}, [%4];"                                      \
                 : "=r"((r)[0]), "=r"((r)[1]), "=r"((r)[2]), "=r"((r)[3])    \
                 : "r"(a))

#define LDSM_X2(r, a)                                                        \
    asm volatile("ldmatrix.sync.aligned.m8n8.x2.shared.b16 "                 \
                 "{%0,%1}, [%2];"                                            \
                 : "=r"((r)[0]), "=r"((r)[1])                                \
                 : "r"(a))

__device__ __forceinline__ void mma16816(float* d, const uint32_t* a,
                                         uint32_t b0, uint32_t b1) {
    asm volatile(
        "mma.sync.aligned.m16n8k16.row.col.f32.bf16.bf16.f32 "
        "{%0,%1,%2,%3}, {%4,%5,%6,%7}, {%8,%9}, {%0,%1,%2,%3};"
        : "+f"(d[0]), "+f"(d[1]), "+f"(d[2]), "+f"(d[3])
        : "r"(a[0]), "r"(a[1]), "r"(a[2]), "r"(a[3]), "r"(b0), "r"(b1));
}

// ---------------------------------------------------------------------------
// edge kernel: exact two-stage edges + builds B table (32 blocks x 80 entries)
// ---------------------------------------------------------------------------
__global__ void pqmf_edge_kernel(const float* __restrict__ x,
                                 const float* __restrict__ qmf,
                                 float* __restrict__ y) {
    __shared__ float s_q[260];
    __shared__ float s_sub[4][16];
    __shared__ float s_part[128];

    const int side = blockIdx.x;
    const int b    = blockIdx.y;
    const float* xb = x + (size_t)b * L_TOT;
    float*       yb = y + (size_t)b * L_TOT;
    const int tid = threadIdx.x;

    for (int i = tid; i < 260; i += 128) s_q[i] = qmf[i];
    __syncthreads();

    // ---- build B[c][k] = C[c&3][k-c], bf16 hi/lo pair-packed --------------
    {
        const int bid = blockIdx.y * 2 + blockIdx.x;    // 0..31
        const int base = bid * 80;
        for (int e = tid; e < 80; e += 128) {
            int idx = base + e;
            int c = idx / 80, kp = idx % 80;
            float v[2];
            #pragma unroll
            for (int u = 0; u < 2; u++) {
                int k = 2 * kp + u, dd = k - c;
                float val = 0.f;
                if (dd >= 0 && dd <= 128) {
                    int r = c & 3, t0 = (4 - r) & 3;
                    for (int t = t0; t <= 64; t += 4) {
                        int s = dd - t;
                        if (s >= 0 && s <= 64) {
                            #pragma unroll
                            for (int q = 0; q < 4; q++)
                                val += s_q[q * 65 + t] * s_q[q * 65 + s];
                        }
                    }
                }
                v[u] = val;
            }
            __nv_bfloat16 h0 = __float2bfloat16(v[0]);
            __nv_bfloat16 h1 = __float2bfloat16(v[1]);
            __nv_bfloat16 l0 = __float2bfloat16(v[0] - __bfloat162float(h0));
            __nv_bfloat16 l1 = __float2bfloat16(v[1] - __bfloat162float(h1));
            g_Bh[idx] = ((uint32_t)__bfloat16_as_ushort(h1) << 16) |
                        __bfloat16_as_ushort(h0);
            g_Bl[idx] = ((uint32_t)__bfloat16_as_ushort(l1) << 16) |
                        __bfloat16_as_ushort(l0);
        }
    }

    // ---- exact edges --------------------------------------------------------
    const int mbase = side ? (M_TOT - 16) : 0;
    if (tid < 64) {
        int k = tid & 3, j = tid >> 2;
        int m = mbase + j;
        float sub = 0.f;
        int pbase = 4 * m - 32;
        for (int s = 0; s <= 64; s++) {
            int pos = pbase + s;
            if (pos >= 0 && pos < L_TOT)
                sub = fmaf(s_q[k * 65 + s], xb[pos], sub);
        }
        s_sub[k][j] = sub;
    }
    __syncthreads();

    float partial = 0.f;
    {
        int nn = tid >> 2, k = tid & 3;
        int n  = side ? (L_TOT - 32 + nn) : nn;
        int t0 = (4 - (n & 3)) & 3;
        for (int t = t0; t <= 64; t += 4) {
            int m = (n + t - 32) >> 2;
            if (m < 0 || m >= M_TOT) continue;
            partial = fmaf(s_q[k * 65 + t], s_sub[k][m - mbase], partial);
        }
    }
    s_part[tid] = partial;
    __syncthreads();
    if (tid < 32) {
        int n = side ? (L_TOT - 32 + tid) : tid;
        yb[n] = s_part[tid * 4] + s_part[tid * 4 + 1] +
                s_part[tid * 4 + 2] + s_part[tid * 4 + 3];
    }
}

// ---------------------------------------------------------------------------
// main: bf16 mma.sync GEMM on the Toeplitz view of x (3-pass hi/lo)
// operands loaded with ldmatrix (conflict-free by layout construction)
// ---------------------------------------------------------------------------
__global__ __launch_bounds__(256, 4)
void pqmf_mma_kernel(const float* __restrict__ x, float* __restrict__ y) {
    __shared__ uint32_t xs_h[XS_WORDS], xs_l[XS_WORDS];
    __shared__ uint32_t bs_h[BS_WORDS], bs_l[BS_WORDS];

    const int tid  = threadIdx.x;
    const int wt   = tid >> 5;     // warp = m-tile (16 rows)
    const int lane = tid & 31;
    const int g    = lane >> 2;    // groupID
    const int tg   = lane & 3;     // threadID-in-group

    const int task = blockIdx.x;
    const int tile = task & (NTILES - 1);
    const int b    = task >> 7;
    const int t0   = tile * TILE_Y;
    const float* xb = x + (size_t)b * L_TOT;
    float*       yb = y + (size_t)b * L_TOT;

    // stage B (pair word kp of row c at bs[c*100 + kp]) — L2-resident
    for (int i = tid; i < 32 * 80; i += 256) {
        int c = i / 80, kp = i % 80;
        bs_h[c * BS_STRIDE + kp] = g_Bh[i];
        bs_l[c * BS_STRIDE + kp] = g_Bl[i];
    }

    // stage x tile: element pair i2 -> skewed word i2 + 4*(i2>>4)
    for (int i2 = tid; i2 < 2112; i2 += 256) {
        int pos = t0 - 64 + 2 * i2;
        float v0 = 0.f, v1 = 0.f;
        if (pos >= 0 && pos + 1 < L_TOT) {
            float2 xv = *reinterpret_cast<const float2*>(xb + pos);
            v0 = xv.x; v1 = xv.y;
        } else {
            if (pos >= 0 && pos < L_TOT)         v0 = xb[pos];
            if (pos + 1 >= 0 && pos + 1 < L_TOT) v1 = xb[pos + 1];
        }
        __nv_bfloat16 h0 = __float2bfloat16(v0);
        __nv_bfloat16 h1 = __float2bfloat16(v1);
        __nv_bfloat16 l0 = __float2bfloat16(v0 - __bfloat162float(h0));
        __nv_bfloat16 l1 = __float2bfloat16(v1 - __bfloat162float(h1));
        int pw = i2 + 4 * (i2 >> 4);
        xs_h[pw] = ((uint32_t)__bfloat16_as_ushort(h1) << 16) |
                   __bfloat16_as_ushort(h0);
        xs_l[pw] = ((uint32_t)__bfloat16_as_ushort(l1) << 16) |
                   __bfloat16_as_ushort(l0);
    }
    __syncthreads();

    // ldmatrix per-lane base addresses (bytes)
    // A x4: matrix j = lane>>3; row = (lane&7) + 8*(j&1); k-half = j>>1
    const int a_row  = (lane & 7) + 8 * ((lane >> 3) & 1);
    const int a_off4 = 4 * (320 * wt + 20 * a_row + 4 * (lane >> 4));
    const uint32_t a_h_base = smem_u32(xs_h) + a_off4;
    const uint32_t a_l_base = smem_u32(xs_l) + a_off4;
    // B x2 (non-trans): lanes 0-7 -> matrix 0 (k-lo half), 8-15 -> matrix 1 (k-hi)
    const int bl_   = lane & 15;
    const int b_off4 = 4 * ((bl_ & 7) * BS_STRIDE + (bl_ >> 3) * 4);
    const uint32_t b_h_base = smem_u32(bs_h) + b_off4;
    const uint32_t b_l_base = smem_u32(bs_l) + b_off4;

    float d[4][4];
    #pragma unroll
    for (int nt = 0; nt < 4; nt++)
        #pragma unroll
        for (int q = 0; q < 4; q++) d[nt][q] = 0.f;

    #pragma unroll
    for (int s = 0; s < 10; s++) {
        const int soff = 4 * (8 * s + 4 * (s >> 1));   // compile-time
        uint32_t ah[4], al[4];
        LDSM_X4(ah, a_h_base + soff);
        LDSM_X4(al, a_l_base + soff);
        #pragma unroll
        for (int nt = 0; nt < 4; nt++) {
            const int bo = 4 * (800 * nt + 8 * s);     // compile-time
            uint32_t bh[2], bl2[2];
            LDSM_X2(bh,  b_h_base + bo);
            LDSM_X2(bl2, b_l_base + bo);
            mma16816(d[nt], ah, bh[0], bh[1]);    // hi*hi
            mma16816(d[nt], al, bh[0], bh[1]);    // lo*hi
            mma16816(d[nt], ah, bl2[0], bl2[1]);  // hi*lo
        }
    }

    // epilogue: d[nt] rows (16wt+g, +8), cols 8nt + 2tg + {0,1}
    const int row0 = 16 * wt + g;
    const bool skip_lo = (tile == 0) && (row0 == 0);
    const bool skip_hi = (tile == NTILES - 1) && (row0 + 8 == 127);
    #pragma unroll
    for (int nt = 0; nt < 4; nt++) {
        int n_lo = t0 + 32 * row0 + 8 * nt + 2 * tg;
        if (!skip_lo)
            *reinterpret_cast<float2*>(yb + n_lo) =
                make_float2(d[nt][0], d[nt][1]);
        if (!skip_hi)
            *reinterpret_cast<float2*>(yb + n_lo + 256) =
                make_float2(d[nt][2], d[nt][3]);
    }
}

extern "C" void kernel_launch(void* const* d_in, const int* in_sizes, int n_in,
                              void* d_out, int out_size) {
    const float* x   = (const float*)d_in[0];
    const float* qmf = (const float*)d_in[1];
    if (n_in >= 2 && in_sizes[0] == 260) {
        x   = (const float*)d_in[1];
        qmf = (const float*)d_in[0];
    }
    float* y = (float*)d_out;

    pqmf_edge_kernel<<<dim3(2, NBATCH), 128>>>(x, qmf, y);
    pqmf_mma_kernel<<<NTASKS, 256>>>(x, y);
}

// round 13
// speedup vs baseline: 1.1550x; 1.0969x over previous
#include <cuda_runtime.h>
#include <cuda_fp16.h>
#include <cstdint>

#define L_TOT    524288
#define M_TOT    (L_TOT / 4)
#define NBATCH   16
#define TILE_Y   4096
#define NTILES   (L_TOT / TILE_Y)      // 128
#define NTASKS   (NTILES * NBATCH)     // 2048

// xs: 4224 fp32 -> 2112 fp16-pair words; skewed: 2112 + 4*(2112/16) = 2640
#define XS_WORDS   2640
#define BS_STRIDE  100                 // words per c-row (100 mod 32 = 4)
#define BS_WORDS   (32 * BS_STRIDE)

// slab s contributes to n-group nt iff B has support there (compile-time)
#define SLAB_ACTIVE(s, nt) ((16*(s)+15 >= 8*(nt)) && (16*(s) <= 8*(nt)+135))

// B operand (fp16 pair packed: hi part and lo correction) via device globals
__device__ uint32_t g_Bh[32 * 80];
__device__ uint32_t g_Bl[32 * 80];

__device__ __forceinline__ uint32_t smem_u32(const void* p) {
    uint32_t a;
    asm("{ .reg .u64 t; cvta.to.shared.u64 t, %1; cvt.u32.u64 %0, t; }"
        : "=r"(a) : "l"(p));
    return a;
}

#define LDSM_X4(r, a)                                                        \
    asm volatile("ldmatrix.sync.aligned.m8n8.x4.shared.b16 "                 \
                 "{%0,%1,%2,%3}, [%4];"                                      \
                 : "=r"((r)[0]), "=r"((r)[1]), "=r"((r)[2]), "=r"((r)[3])    \
                 : "r"(a))

#define LDSM_X2(r, a)                                                        \
    asm volatile("ldmatrix.sync.aligned.m8n8.x2.shared.b16 "                 \
                 "{%0,%1}, [%2];"                                            \
                 : "=r"((r)[0]), "=r"((r)[1])                                \
                 : "r"(a))

__device__ __forceinline__ void mma16816(float* d, const uint32_t* a,
                                         uint32_t b0, uint32_t b1) {
    asm volatile(
        "mma.sync.aligned.m16n8k16.row.col.f32.f16.f16.f32 "
        "{%0,%1,%2,%3}, {%4,%5,%6,%7}, {%8,%9}, {%0,%1,%2,%3};"
        : "+f"(d[0]), "+f"(d[1]), "+f"(d[2]), "+f"(d[3])
        : "r"(a[0]), "r"(a[1]), "r"(a[2]), "r"(a[3]), "r"(b0), "r"(b1));
}

// ---------------------------------------------------------------------------
// edge kernel: exact two-stage edges + builds B table (32 blocks x 80 entries)
// ---------------------------------------------------------------------------
__global__ void pqmf_edge_kernel(const float* __restrict__ x,
                                 const float* __restrict__ qmf,
                                 float* __restrict__ y) {
    __shared__ float s_q[260];
    __shared__ float s_sub[4][16];
    __shared__ float s_part[128];

    const int side = blockIdx.x;
    const int b    = blockIdx.y;
    const float* xb = x + (size_t)b * L_TOT;
    float*       yb = y + (size_t)b * L_TOT;
    const int tid = threadIdx.x;

    for (int i = tid; i < 260; i += 128) s_q[i] = qmf[i];
    __syncthreads();

    // ---- build B[c][k] = C[c&3][k-c], fp16 hi + fp16 lo correction --------
    {
        const int bid = blockIdx.y * 2 + blockIdx.x;    // 0..31
        const int base = bid * 80;
        for (int e = tid; e < 80; e += 128) {
            int idx = base + e;
            int c = idx / 80, kp = idx % 80;
            float v[2];
            #pragma unroll
            for (int u = 0; u < 2; u++) {
                int k = 2 * kp + u, dd = k - c;
                float val = 0.f;
                if (dd >= 0 && dd <= 128) {
                    int r = c & 3, t0 = (4 - r) & 3;
                    for (int t = t0; t <= 64; t += 4) {
                        int s = dd - t;
                        if (s >= 0 && s <= 64) {
                            #pragma unroll
                            for (int q = 0; q < 4; q++)
                                val += s_q[q * 65 + t] * s_q[q * 65 + s];
                        }
                    }
                }
                v[u] = val;
            }
            __half h0 = __float2half_rn(v[0]);
            __half h1 = __float2half_rn(v[1]);
            __half l0 = __float2half_rn(v[0] - __half2float(h0));
            __half l1 = __float2half_rn(v[1] - __half2float(h1));
            g_Bh[idx] = ((uint32_t)__half_as_ushort(h1) << 16) |
                        __half_as_ushort(h0);
            g_Bl[idx] = ((uint32_t)__half_as_ushort(l1) << 16) |
                        __half_as_ushort(l0);
        }
    }

    // ---- exact edges --------------------------------------------------------
    const int mbase = side ? (M_TOT - 16) : 0;
    if (tid < 64) {
        int k = tid & 3, j = tid >> 2;
        int m = mbase + j;
        float sub = 0.f;
        int pbase = 4 * m - 32;
        for (int s = 0; s <= 64; s++) {
            int pos = pbase + s;
            if (pos >= 0 && pos < L_TOT)
                sub = fmaf(s_q[k * 65 + s], xb[pos], sub);
        }
        s_sub[k][j] = sub;
    }
    __syncthreads();

    float partial = 0.f;
    {
        int nn = tid >> 2, k = tid & 3;
        int n  = side ? (L_TOT - 32 + nn) : nn;
        int t0 = (4 - (n & 3)) & 3;
        for (int t = t0; t <= 64; t += 4) {
            int m = (n + t - 32) >> 2;
            if (m < 0 || m >= M_TOT) continue;
            partial = fmaf(s_q[k * 65 + t], s_sub[k][m - mbase], partial);
        }
    }
    s_part[tid] = partial;
    __syncthreads();
    if (tid < 32) {
        int n = side ? (L_TOT - 32 + tid) : tid;
        yb[n] = s_part[tid * 4] + s_part[tid * 4 + 1] +
                s_part[tid * 4 + 2] + s_part[tid * 4 + 3];
    }
}

// ---------------------------------------------------------------------------
// main: fp16 mma.sync GEMM on the Toeplitz view of x
// 2 passes: A_f16 * B_hi + A_f16 * B_lo (B pair represents filter to ~2^-22)
// banded-support slab skipping (9 of 10 slabs per n-group)
// ---------------------------------------------------------------------------
__global__ __launch_bounds__(256, 4)
void pqmf_mma_kernel(const float* __restrict__ x, float* __restrict__ y) {
    __shared__ uint32_t xs[XS_WORDS];
    __shared__ uint32_t bs_h[BS_WORDS], bs_l[BS_WORDS];

    const int tid  = threadIdx.x;
    const int wt   = tid >> 5;     // warp = m-tile (16 rows)
    const int lane = tid & 31;
    const int g    = lane >> 2;    // groupID
    const int tg   = lane & 3;     // threadID-in-group

    const int task = blockIdx.x;
    const int tile = task & (NTILES - 1);
    const int b    = task >> 7;
    const int t0   = tile * TILE_Y;
    const float* xb = x + (size_t)b * L_TOT;
    float*       yb = y + (size_t)b * L_TOT;

    // stage B (pair word kp of row c at bs[c*100 + kp]) — L2-resident
    for (int i = tid; i < 32 * 80; i += 256) {
        int c = i / 80, kp = i % 80;
        bs_h[c * BS_STRIDE + kp] = g_Bh[i];
        bs_l[c * BS_STRIDE + kp] = g_Bl[i];
    }

    // stage x tile: element pair i2 -> skewed word i2 + 4*(i2>>4), fp16
    for (int i2 = tid; i2 < 2112; i2 += 256) {
        int pos = t0 - 64 + 2 * i2;
        float v0 = 0.f, v1 = 0.f;
        if (pos >= 0 && pos + 1 < L_TOT) {
            float2 xv = *reinterpret_cast<const float2*>(xb + pos);
            v0 = xv.x; v1 = xv.y;
        } else {
            if (pos >= 0 && pos < L_TOT)         v0 = xb[pos];
            if (pos + 1 >= 0 && pos + 1 < L_TOT) v1 = xb[pos + 1];
        }
        __half h0 = __float2half_rn(v0);
        __half h1 = __float2half_rn(v1);
        int pw = i2 + 4 * (i2 >> 4);
        xs[pw] = ((uint32_t)__half_as_ushort(h1) << 16) |
                 __half_as_ushort(h0);
    }
    __syncthreads();

    // ldmatrix per-lane base addresses (bytes)
    const int a_row  = (lane & 7) + 8 * ((lane >> 3) & 1);
    const int a_off4 = 4 * (320 * wt + 20 * a_row + 4 * (lane >> 4));
    const uint32_t a_base = smem_u32(xs) + a_off4;
    const int bl_   = lane & 15;
    const int b_off4 = 4 * ((bl_ & 7) * BS_STRIDE + (bl_ >> 3) * 4);
    const uint32_t b_h_base = smem_u32(bs_h) + b_off4;
    const uint32_t b_l_base = smem_u32(bs_l) + b_off4;

    float d[4][4];
    #pragma unroll
    for (int nt = 0; nt < 4; nt++)
        #pragma unroll
        for (int q = 0; q < 4; q++) d[nt][q] = 0.f;

    #pragma unroll
    for (int s = 0; s < 10; s++) {
        const int soff = 4 * (8 * s + 4 * (s >> 1));   // compile-time
        uint32_t a[4];
        LDSM_X4(a, a_base + soff);
        uint32_t bh[4][2], bl2[4][2];
        #pragma unroll
        for (int nt = 0; nt < 4; nt++) {
            if (SLAB_ACTIVE(s, nt)) {
                const int bo = 4 * (800 * nt + 8 * s); // compile-time
                LDSM_X2(bh[nt],  b_h_base + bo);
                LDSM_X2(bl2[nt], b_l_base + bo);
            }
        }
        // pass-major: same-accumulator MMAs are 4 independent chains apart
        #pragma unroll
        for (int nt = 0; nt < 4; nt++)
            if (SLAB_ACTIVE(s, nt))
                mma16816(d[nt], a, bh[nt][0], bh[nt][1]);
        #pragma unroll
        for (int nt = 0; nt < 4; nt++)
            if (SLAB_ACTIVE(s, nt))
                mma16816(d[nt], a, bl2[nt][0], bl2[nt][1]);
    }

    // epilogue: d[nt] rows (16wt+g, +8), cols 8nt + 2tg + {0,1}
    const int row0 = 16 * wt + g;
    const bool skip_lo = (tile == 0) && (row0 == 0);
    const bool skip_hi = (tile == NTILES - 1) && (row0 + 8 == 127);
    #pragma unroll
    for (int nt = 0; nt < 4; nt++) {
        int n_lo = t0 + 32 * row0 + 8 * nt + 2 * tg;
        if (!skip_lo)
            *reinterpret_cast<float2*>(yb + n_lo) =
                make_float2(d[nt][0], d[nt][1]);
        if (!skip_hi)
            *reinterpret_cast<float2*>(yb + n_lo + 256) =
                make_float2(d[nt][2], d[nt][3]);
    }
}

extern "C" void kernel_launch(void* const* d_in, const int* in_sizes, int n_in,
                              void* d_out, int out_size) {
    const float* x   = (const float*)d_in[0];
    const float* qmf = (const float*)d_in[1];
    if (n_in >= 2 && in_sizes[0] == 260) {
        x   = (const float*)d_in[1];
        qmf = (const float*)d_in[0];
    }
    float* y = (float*)d_out;

    pqmf_edge_kernel<<<dim3(2, NBATCH), 128>>>(x, qmf, y);
    pqmf_mma_kernel<<<NTASKS, 256>>>(x, y);
}

// round 14
// speedup vs baseline: 1.3424x; 1.1623x over previous
#include <cuda_runtime.h>
#include <cuda_fp16.h>
#include <cstdint>

#define L_TOT    524288
#define M_TOT    (L_TOT / 4)
#define NBATCH   16
#define TILE_Y   4096
#define NTILES   (L_TOT / TILE_Y)      // 128
#define NTASKS   (NTILES * NBATCH)     // 2048
#define GRID_MAIN 512
#define TPC      (NTASKS / GRID_MAIN)  // 4

// xs: 4224 fp32 -> 2112 fp16-pair words; skewed: 2112 + 4*(2112/16) = 2640
#define XS_WORDS   2640
#define BS_STRIDE  100                 // words per c-row (100 mod 32 = 4)
#define BS_WORDS   (32 * BS_STRIDE)    // 3200 (cols 80..99 unused padding)

// slab s contributes to n-group nt iff B has support there (compile-time)
#define SLAB_ACTIVE(s, nt) ((16*(s)+15 >= 8*(nt)) && (16*(s) <= 8*(nt)+135))

// B operand in gmem, laid out EXACTLY like the smem staging buffer
__device__ uint32_t g_Bh[BS_WORDS];
__device__ uint32_t g_Bl[BS_WORDS];

__device__ __forceinline__ uint32_t smem_u32(const void* p) {
    uint32_t a;
    asm("{ .reg .u64 t; cvta.to.shared.u64 t, %1; cvt.u32.u64 %0, t; }"
        : "=r"(a) : "l"(p));
    return a;
}

#define LDSM_X4(r, a)                                                        \
    asm volatile("ldmatrix.sync.aligned.m8n8.x4.shared.b16 "                 \
                 "{%0,%1,%2,%3}, [%4];"                                      \
                 : "=r"((r)[0]), "=r"((r)[1]), "=r"((r)[2]), "=r"((r)[3])    \
                 : "r"(a))

#define LDSM_X2(r, a)                                                        \
    asm volatile("ldmatrix.sync.aligned.m8n8.x2.shared.b16 "                 \
                 "{%0,%1}, [%2];"                                            \
                 : "=r"((r)[0]), "=r"((r)[1])                                \
                 : "r"(a))

__device__ __forceinline__ void mma16816(float* d, const uint32_t* a,
                                         uint32_t b0, uint32_t b1) {
    asm volatile(
        "mma.sync.aligned.m16n8k16.row.col.f32.f16.f16.f32 "
        "{%0,%1,%2,%3}, {%4,%5,%6,%7}, {%8,%9}, {%0,%1,%2,%3};"
        : "+f"(d[0]), "+f"(d[1]), "+f"(d[2]), "+f"(d[3])
        : "r"(a[0]), "r"(a[1]), "r"(a[2]), "r"(a[3]), "r"(b0), "r"(b1));
}

// ---------------------------------------------------------------------------
// edge kernel: exact two-stage edges + builds B table (32 blocks x 80 entries)
// ---------------------------------------------------------------------------
__global__ void pqmf_edge_kernel(const float* __restrict__ x,
                                 const float* __restrict__ qmf,
                                 float* __restrict__ y) {
    __shared__ float s_q[260];
    __shared__ float s_sub[4][16];
    __shared__ float s_part[128];

    const int side = blockIdx.x;
    const int b    = blockIdx.y;
    const float* xb = x + (size_t)b * L_TOT;
    float*       yb = y + (size_t)b * L_TOT;
    const int tid = threadIdx.x;

    for (int i = tid; i < 260; i += 128) s_q[i] = qmf[i];
    __syncthreads();

    // ---- build B[c][k] = C[c&3][k-c], fp16 hi + fp16 lo correction --------
    {
        const int bid = blockIdx.y * 2 + blockIdx.x;    // 0..31, = row c
        const int c = bid;
        for (int kp = tid; kp < BS_STRIDE; kp += 128) {  // fill padding too
            float v[2];
            #pragma unroll
            for (int u = 0; u < 2; u++) {
                int k = 2 * kp + u, dd = k - c;
                float val = 0.f;
                if (kp < 80 && dd >= 0 && dd <= 128) {
                    int r = c & 3, t0 = (4 - r) & 3;
                    for (int t = t0; t <= 64; t += 4) {
                        int s = dd - t;
                        if (s >= 0 && s <= 64) {
                            #pragma unroll
                            for (int q = 0; q < 4; q++)
                                val += s_q[q * 65 + t] * s_q[q * 65 + s];
                        }
                    }
                }
                v[u] = val;
            }
            __half h0 = __float2half_rn(v[0]);
            __half h1 = __float2half_rn(v[1]);
            __half l0 = __float2half_rn(v[0] - __half2float(h0));
            __half l1 = __float2half_rn(v[1] - __half2float(h1));
            g_Bh[c * BS_STRIDE + kp] = ((uint32_t)__half_as_ushort(h1) << 16) |
                                       __half_as_ushort(h0);
            g_Bl[c * BS_STRIDE + kp] = ((uint32_t)__half_as_ushort(l1) << 16) |
                                       __half_as_ushort(l0);
        }
    }

    // ---- exact edges --------------------------------------------------------
    const int mbase = side ? (M_TOT - 16) : 0;
    if (tid < 64) {
        int k = tid & 3, j = tid >> 2;
        int m = mbase + j;
        float sub = 0.f;
        int pbase = 4 * m - 32;
        for (int s = 0; s <= 64; s++) {
            int pos = pbase + s;
            if (pos >= 0 && pos < L_TOT)
                sub = fmaf(s_q[k * 65 + s], xb[pos], sub);
        }
        s_sub[k][j] = sub;
    }
    __syncthreads();

    float partial = 0.f;
    {
        int nn = tid >> 2, k = tid & 3;
        int n  = side ? (L_TOT - 32 + nn) : nn;
        int t0 = (4 - (n & 3)) & 3;
        for (int t = t0; t <= 64; t += 4) {
            int m = (n + t - 32) >> 2;
            if (m < 0 || m >= M_TOT) continue;
            partial = fmaf(s_q[k * 65 + t], s_sub[k][m - mbase], partial);
        }
    }
    s_part[tid] = partial;
    __syncthreads();
    if (tid < 32) {
        int n = side ? (L_TOT - 32 + tid) : tid;
        yb[n] = s_part[tid * 4] + s_part[tid * 4 + 1] +
                s_part[tid * 4 + 2] + s_part[tid * 4 + 3];
    }
}

// ---------------------------------------------------------------------------
// x-tile prefetch: 1056 uint4 per tile; thread holds <=5 in registers
// ---------------------------------------------------------------------------
__device__ __forceinline__ void load_x_regs(const float* __restrict__ x,
                                            int task, int tid, uint4 xr[5]) {
    const int tile = task & (NTILES - 1);
    const int b    = task >> 7;
    const int t0   = tile * TILE_Y;
    const float* xb = x + (size_t)b * L_TOT;
    const bool edge = (tile == 0) || (tile == NTILES - 1);
    #pragma unroll
    for (int j = 0; j < 5; j++) {
        int idx = tid + 256 * j;
        if (idx < 1056) {
            int pos = t0 - 64 + 4 * idx;
            if (!edge) {
                xr[j] = *reinterpret_cast<const uint4*>(xb + pos);
            } else {
                float f[4];
                #pragma unroll
                for (int u = 0; u < 4; u++) {
                    int p = pos + u;
                    f[u] = (p >= 0 && p < L_TOT) ? xb[p] : 0.f;
                }
                xr[j] = make_uint4(__float_as_uint(f[0]), __float_as_uint(f[1]),
                                   __float_as_uint(f[2]), __float_as_uint(f[3]));
            }
        }
    }
}

__device__ __forceinline__ void sts_x(uint32_t* __restrict__ xs,
                                      int tid, const uint4 xr[5]) {
    #pragma unroll
    for (int j = 0; j < 5; j++) {
        int idx = tid + 256 * j;
        if (idx < 1056) {
            __half2 w0 = __floats2half2_rn(__uint_as_float(xr[j].x),
                                           __uint_as_float(xr[j].y));
            __half2 w1 = __floats2half2_rn(__uint_as_float(xr[j].z),
                                           __uint_as_float(xr[j].w));
            int i2 = 2 * idx;
            int pw = i2 + 4 * (i2 >> 4);      // pw even; pw+1 same skew group
            *reinterpret_cast<uint2*>(&xs[pw]) =
                make_uint2(*reinterpret_cast<uint32_t*>(&w0),
                           *reinterpret_cast<uint32_t*>(&w1));
        }
    }
}

// ---------------------------------------------------------------------------
// main: fp16 mma.sync GEMM on the Toeplitz view of x; persistent CTAs with
// register prefetch of the next x tile overlapping the current mainloop
// ---------------------------------------------------------------------------
__global__ __launch_bounds__(256, 3)
void pqmf_mma_kernel(const float* __restrict__ x, float* __restrict__ y) {
    __shared__ __align__(16) uint32_t xs[XS_WORDS];
    __shared__ __align__(16) uint32_t bs_h[BS_WORDS], bs_l[BS_WORDS];

    const int tid  = threadIdx.x;
    const int wt   = tid >> 5;
    const int lane = tid & 31;
    const int g    = lane >> 2;
    const int tg   = lane & 3;

    // stage B once: straight uint4 copy (layouts match)
    #pragma unroll
    for (int j = 0; j < 4; j++) {
        int i = tid + 256 * j;
        if (i < BS_WORDS / 4) {
            reinterpret_cast<uint4*>(bs_h)[i] =
                reinterpret_cast<const uint4*>(g_Bh)[i];
            reinterpret_cast<uint4*>(bs_l)[i] =
                reinterpret_cast<const uint4*>(g_Bl)[i];
        }
    }

    uint4 xr[5];
    load_x_regs(x, blockIdx.x, tid, xr);
    sts_x(xs, tid, xr);
    __syncthreads();

    // ldmatrix per-lane base addresses (bytes) — xs/bs buffers are reused
    const int a_row  = (lane & 7) + 8 * ((lane >> 3) & 1);
    const int a_off4 = 4 * (320 * wt + 20 * a_row + 4 * (lane >> 4));
    const uint32_t a_base = smem_u32(xs) + a_off4;
    const int bl_   = lane & 15;
    const int b_off4 = 4 * ((bl_ & 7) * BS_STRIDE + (bl_ >> 3) * 4);
    const uint32_t b_h_base = smem_u32(bs_h) + b_off4;
    const uint32_t b_l_base = smem_u32(bs_l) + b_off4;

    for (int it = 0; it < TPC; it++) {
        const int task = blockIdx.x + it * GRID_MAIN;
        const int tile = task & (NTILES - 1);
        const int b    = task >> 7;
        const int t0   = tile * TILE_Y;
        float* yb = y + (size_t)b * L_TOT;

        const bool have_next = (it + 1 < TPC);
        if (have_next)
            load_x_regs(x, task + GRID_MAIN, tid, xr);   // overlaps mainloop

        float d[4][4];
        #pragma unroll
        for (int nt = 0; nt < 4; nt++)
            #pragma unroll
            for (int q = 0; q < 4; q++) d[nt][q] = 0.f;

        #pragma unroll
        for (int s = 0; s < 10; s++) {
            const int soff = 4 * (8 * s + 4 * (s >> 1));
            uint32_t a[4];
            LDSM_X4(a, a_base + soff);
            uint32_t bh[4][2], bl2[4][2];
            #pragma unroll
            for (int nt = 0; nt < 4; nt++) {
                if (SLAB_ACTIVE(s, nt)) {
                    const int bo = 4 * (800 * nt + 8 * s);
                    LDSM_X2(bh[nt],  b_h_base + bo);
                    LDSM_X2(bl2[nt], b_l_base + bo);
                }
            }
            #pragma unroll
            for (int nt = 0; nt < 4; nt++)
                if (SLAB_ACTIVE(s, nt))
                    mma16816(d[nt], a, bh[nt][0], bh[nt][1]);
            #pragma unroll
            for (int nt = 0; nt < 4; nt++)
                if (SLAB_ACTIVE(s, nt))
                    mma16816(d[nt], a, bl2[nt][0], bl2[nt][1]);
        }

        // epilogue
        const int row0 = 16 * wt + g;
        const bool skip_lo = (tile == 0) && (row0 == 0);
        const bool skip_hi = (tile == NTILES - 1) && (row0 + 8 == 127);
        #pragma unroll
        for (int nt = 0; nt < 4; nt++) {
            int n_lo = t0 + 32 * row0 + 8 * nt + 2 * tg;
            if (!skip_lo)
                *reinterpret_cast<float2*>(yb + n_lo) =
                    make_float2(d[nt][0], d[nt][1]);
            if (!skip_hi)
                *reinterpret_cast<float2*>(yb + n_lo + 256) =
                    make_float2(d[nt][2], d[nt][3]);
        }

        if (have_next) {
            __syncthreads();          // all warps done reading xs
            sts_x(xs, tid, xr);
            __syncthreads();          // new tile visible
        }
    }
}

extern "C" void kernel_launch(void* const* d_in, const int* in_sizes, int n_in,
                              void* d_out, int out_size) {
    const float* x   = (const float*)d_in[0];
    const float* qmf = (const float*)d_in[1];
    if (n_in >= 2 && in_sizes[0] == 260) {
        x   = (const float*)d_in[1];
        qmf = (const float*)d_in[0];
    }
    float* y = (float*)d_out;

    pqmf_edge_kernel<<<dim3(2, NBATCH), 128>>>(x, qmf, y);
    pqmf_mma_kernel<<<GRID_MAIN, 256>>>(x, y);
}